// round 13
// baseline (speedup 1.0000x reference)
#include <cuda_runtime.h>
#include <math.h>

#define Bq 8
#define Cc 192
#define HH 128
#define WW 128
#define HWsz (HH*WW)      // 16384
#define C3 (3*Cc)         // 576
#define NHEADS 4
#define Dh 48             // C / heads

// ---- scratch (device globals: no cudaMalloc allowed) ----
__device__ float g_qkv[(long)Bq*C3*HWsz];    // after 1x1 conv
__device__ float g_qkvdw[(long)Bq*C3*HWsz];  // after depthwise 3x3 (v part used)
__device__ float g_norms[Bq*2*Cc];           // sum of squares for q,k rows
__device__ float g_gram[Bq*NHEADS*Dh*Dh];    // raw gram -> attn (in place)
__device__ float g_M[Bq*Cc*Cc];              // proj_w folded with attn

// ---------------- zero init ----------------
__global__ void zero_kernel(float* p0, int n0, float* p1, int n1) {
    int i = blockIdx.x * blockDim.x + threadIdx.x;
    if (i < n0) p0[i] = 0.f;
    if (i < n1) p1[i] = 0.f;
}

// ---------------- helpers ----------------
__device__ __forceinline__ unsigned f2tf32(float x) {
    unsigned r;
    asm("cvt.rna.tf32.f32 %0, %1;" : "=r"(r) : "f"(x));
    return r;
}
__device__ __forceinline__ void mma_tf32(float* c, const unsigned* a,
                                         unsigned b0, unsigned b1) {
    asm volatile(
        "mma.sync.aligned.m16n8k8.row.col.f32.tf32.tf32.f32 "
        "{%0,%1,%2,%3}, {%4,%5,%6,%7}, {%8,%9}, {%0,%1,%2,%3};"
        : "+f"(c[0]), "+f"(c[1]), "+f"(c[2]), "+f"(c[3])
        : "r"(a[0]), "r"(a[1]), "r"(a[2]), "r"(a[3]), "r"(b0), "r"(b1));
}
// depthwise 3x3 on 4 horizontally-adjacent pixels at (y, x..x+3)
__device__ __forceinline__ void conv4(const float* __restrict__ base,
                                      int y, int x,
                                      const float* w, float bv, float* o) {
    float a0 = bv, a1 = bv, a2 = bv, a3 = bv;
    #pragma unroll
    for (int dy = 0; dy < 3; dy++) {
        int yy = y + dy - 1;
        if (yy < 0 || yy >= HH) continue;
        const float* rp = base + yy*WW;
        float4 v = *(const float4*)(rp + x);
        float lf = (x > 0)      ? rp[x-1] : 0.f;
        float rt = (x + 4 < WW) ? rp[x+4] : 0.f;
        float w0 = w[dy*3+0], w1 = w[dy*3+1], w2 = w[dy*3+2];
        a0 = fmaf(w0, lf,  fmaf(w1, v.x, fmaf(w2, v.y, a0)));
        a1 = fmaf(w0, v.x, fmaf(w1, v.y, fmaf(w2, v.z, a1)));
        a2 = fmaf(w0, v.y, fmaf(w1, v.z, fmaf(w2, v.w, a2)));
        a3 = fmaf(w0, v.z, fmaf(w1, v.w, fmaf(w2, rt,  a3)));
    }
    o[0] = a0; o[1] = a1; o[2] = a2; o[3] = a3;
}

// ---------------- tf32 GEMM (R9 config: n-fastest grid) ---------------------
#define GBM 128
#define GBN 128
#define GBK 16
__global__ void __launch_bounds__(256)
tf32_gemm_bias_kernel(const float* __restrict__ A, long sA,
                      const float* __restrict__ B, long sB,
                      float* __restrict__ C, long sC,
                      const float* __restrict__ bias,
                      int M, int N, int K)
{
    __shared__ unsigned As[2][GBM][20];
    __shared__ unsigned Bs[2][GBK][136];

    const int bz = blockIdx.z;
    const float* Ab = A + (long)bz * sA;
    const float* Bb = B + (long)bz * sB;
    float* Cb = C + (long)bz * sC;

    const int m0 = blockIdx.y * GBM;
    const int n0 = blockIdx.x * GBN;
    const int tid  = threadIdx.x;
    const int wid  = tid >> 5;
    const int lane = tid & 31;
    const int gid  = lane >> 2;
    const int tig  = lane & 3;
    const int wm = (wid & 3) * 32;
    const int wn = (wid >> 2) * 64;

    const int am0 = tid >> 2,          ak0 = (tid & 3) << 2;
    const int am1 = (tid + 256) >> 2,  ak1 = ((tid + 256) & 3) << 2;
    const int bk0 = tid >> 5,          bc0 = (tid & 31) << 2;
    const int bk1 = (tid + 256) >> 5,  bc1 = ((tid + 256) & 31) << 2;

    float acc[2][8][4];
    #pragma unroll
    for (int i = 0; i < 2; i++)
        #pragma unroll
        for (int j = 0; j < 8; j++)
            #pragma unroll
            for (int q = 0; q < 4; q++) acc[i][j][q] = 0.f;

    const int NT = K / GBK;

    float4 ra0, ra1, rb0, rb1;
    auto ldg_tile = [&](int it) {
        const int k0 = it * GBK;
        ra0 = (m0 + am0 < M) ? *(const float4*)(Ab + (long)(m0+am0)*K + k0 + ak0)
                             : make_float4(0.f,0.f,0.f,0.f);
        ra1 = (m0 + am1 < M) ? *(const float4*)(Ab + (long)(m0+am1)*K + k0 + ak1)
                             : make_float4(0.f,0.f,0.f,0.f);
        rb0 = *(const float4*)(Bb + (long)(k0+bk0)*N + n0 + bc0);
        rb1 = *(const float4*)(Bb + (long)(k0+bk1)*N + n0 + bc1);
    };
    auto sts_tile = [&](int s) {
        uint4 w;
        w.x = f2tf32(ra0.x); w.y = f2tf32(ra0.y); w.z = f2tf32(ra0.z); w.w = f2tf32(ra0.w);
        *(uint4*)&As[s][am0][ak0] = w;
        w.x = f2tf32(ra1.x); w.y = f2tf32(ra1.y); w.z = f2tf32(ra1.z); w.w = f2tf32(ra1.w);
        *(uint4*)&As[s][am1][ak1] = w;
        w.x = f2tf32(rb0.x); w.y = f2tf32(rb0.y); w.z = f2tf32(rb0.z); w.w = f2tf32(rb0.w);
        *(uint4*)&Bs[s][bk0][bc0] = w;
        w.x = f2tf32(rb1.x); w.y = f2tf32(rb1.y); w.z = f2tf32(rb1.z); w.w = f2tf32(rb1.w);
        *(uint4*)&Bs[s][bk1][bc1] = w;
    };

    ldg_tile(0);
    sts_tile(0);
    if (NT > 1) ldg_tile(1);
    __syncthreads();

    for (int it = 0; it < NT; it++) {
        if (it + 1 < NT) sts_tile((it + 1) & 1);
        if (it + 2 < NT) ldg_tile(it + 2);
        const int s = it & 1;

        #pragma unroll
        for (int ks = 0; ks < GBK; ks += 8) {
            unsigned a[2][4];
            #pragma unroll
            for (int mi = 0; mi < 2; mi++) {
                int mr = wm + mi*16;
                a[mi][0] = As[s][mr + gid    ][ks + tig    ];
                a[mi][1] = As[s][mr + gid + 8][ks + tig    ];
                a[mi][2] = As[s][mr + gid    ][ks + tig + 4];
                a[mi][3] = As[s][mr + gid + 8][ks + tig + 4];
            }
            #pragma unroll
            for (int ni = 0; ni < 8; ni++) {
                int nb = wn + ni*8;
                unsigned b0 = Bs[s][ks + tig    ][nb + gid];
                unsigned b1 = Bs[s][ks + tig + 4][nb + gid];
                #pragma unroll
                for (int mi = 0; mi < 2; mi++)
                    mma_tf32(acc[mi][ni], a[mi], b0, b1);
            }
        }
        __syncthreads();
    }

    #pragma unroll
    for (int mi = 0; mi < 2; mi++) {
        int r0 = m0 + wm + mi*16 + gid;
        int r1 = r0 + 8;
        float bv0 = (r0 < M && bias) ? bias[r0] : 0.f;
        float bv1 = (r1 < M && bias) ? bias[r1] : 0.f;
        #pragma unroll
        for (int ni = 0; ni < 8; ni++) {
            int col = n0 + wn + ni*8 + tig*2;
            if (r0 < M) {
                float2 v; v.x = acc[mi][ni][0] + bv0; v.y = acc[mi][ni][1] + bv0;
                *(float2*)(Cb + (long)r0*N + col) = v;
            }
            if (r1 < M) {
                float2 v; v.x = acc[mi][ni][2] + bv1; v.y = acc[mi][ni][3] + bv1;
                *(float2*)(Cb + (long)r1*N + col) = v;
            }
        }
    }
}

// ---------------- depthwise 3x3 for V channels only --------------------------
__global__ void __launch_bounds__(256)
dwconv_v_kernel(const float* __restrict__ in,   // g_qkv
                const float* __restrict__ w,
                const float* __restrict__ bias,
                float* __restrict__ out)        // g_qkvdw (v region written)
{
    const int bc = blockIdx.x;            // b*Cc + c  (v channels)
    const int b  = bc / Cc;
    const int c  = bc % Cc;
    const int ch = 2*Cc + c;              // channel within C3
    const long choff = ((long)b*C3 + ch) * HWsz;

    const int tid = threadIdx.x;
    const int t = blockIdx.y * 256 + tid;
    const int y  = t >> 5;
    const int x  = (t & 31) << 2;

    const float* ip = in + choff;
    float wv[9];
    #pragma unroll
    for (int i = 0; i < 9; i++) wv[i] = w[ch*9 + i];

    float o[4];
    conv4(ip, y, x, wv, bias[ch], o);
    float4 ov; ov.x = o[0]; ov.y = o[1]; ov.z = o[2]; ov.w = o[3];
    *(float4*)(out + choff + y*WW + x) = ov;
}

// ------- gram via tf32 mma with FUSED depthwise conv on q,k -----------------
// Reads post-1x1 qkv, applies dw 3x3 inline, computes norms + gram.
#define GSPLIT 32
#define GCHUNK (HWsz/GSPLIT)   // 512
#define GTP 32                 // pixels per smem tile
#define GST 36                 // pixel stride (floats)
__global__ void __launch_bounds__(192)
gram_dw_kernel(const float* __restrict__ qkv,
               const float* __restrict__ dww,
               const float* __restrict__ dwb,
               float* __restrict__ gram,
               float* __restrict__ norms)
{
    const int bh = blockIdx.x;
    const int split = blockIdx.y;
    const int b = bh >> 2, h = bh & 3;

    __shared__ float Qs[Dh][GST];
    __shared__ float Ks[Dh][GST];

    const int tid  = threadIdx.x;
    const int wid  = tid >> 5;
    const int lane = tid & 31;
    const int gid  = lane >> 2;
    const int tig  = lane & 3;
    const int mr   = (wid % 3) * 16;
    const int nb0  = (wid / 3) * 24;

    float acc[3][4];
    #pragma unroll
    for (int i = 0; i < 3; i++)
        #pragma unroll
        for (int q = 0; q < 4; q++) acc[i][q] = 0.f;

    const int r0 = tid >> 3;          // 0..23
    const int r1 = r0 + 24;           // 24..47
    const int c0 = (tid & 7) << 2;    // pixel within tile

    // channel indices + conv weights for this thread's 4 rows
    const int cq0 = h*Dh + r0, cq1 = h*Dh + r1;
    const int ck0 = Cc + h*Dh + r0, ck1 = Cc + h*Dh + r1;
    const float* qb0 = qkv + ((long)b*C3 + cq0) * HWsz;
    const float* qb1 = qkv + ((long)b*C3 + cq1) * HWsz;
    const float* kb0 = qkv + ((long)b*C3 + ck0) * HWsz;
    const float* kb1 = qkv + ((long)b*C3 + ck1) * HWsz;
    float wq0[9], wq1[9], wk0[9], wk1[9];
    #pragma unroll
    for (int i = 0; i < 9; i++) {
        wq0[i] = dww[cq0*9 + i];
        wq1[i] = dww[cq1*9 + i];
        wk0[i] = dww[ck0*9 + i];
        wk1[i] = dww[ck1*9 + i];
    }
    const float bq0 = dwb[cq0], bq1 = dwb[cq1];
    const float bk0v = dwb[ck0], bk1v = dwb[ck1];

    float nq0 = 0.f, nq1 = 0.f, nk0 = 0.f, nk1 = 0.f;

    const int nbase = split * GCHUNK;

    for (int t = 0; t < GCHUNK; t += GTP) {
        const int p = nbase + t + c0;
        const int y = p >> 7;
        const int x = p & 127;

        float o[4];
        conv4(qb0, y, x, wq0, bq0, o);
        *(float4*)&Qs[r0][c0] = *(float4*)o;
        nq0 += o[0]*o[0] + o[1]*o[1] + o[2]*o[2] + o[3]*o[3];

        conv4(kb0, y, x, wk0, bk0v, o);
        *(float4*)&Ks[r0][c0] = *(float4*)o;
        nk0 += o[0]*o[0] + o[1]*o[1] + o[2]*o[2] + o[3]*o[3];

        conv4(qb1, y, x, wq1, bq1, o);
        *(float4*)&Qs[r1][c0] = *(float4*)o;
        nq1 += o[0]*o[0] + o[1]*o[1] + o[2]*o[2] + o[3]*o[3];

        conv4(kb1, y, x, wk1, bk1v, o);
        *(float4*)&Ks[r1][c0] = *(float4*)o;
        nk1 += o[0]*o[0] + o[1]*o[1] + o[2]*o[2] + o[3]*o[3];
        __syncthreads();

        #pragma unroll
        for (int ks = 0; ks < GTP; ks += 8) {
            float af[4];
            af[0] = Qs[mr + gid    ][ks + tig    ];
            af[1] = Qs[mr + gid + 8][ks + tig    ];
            af[2] = Qs[mr + gid    ][ks + tig + 4];
            af[3] = Qs[mr + gid + 8][ks + tig + 4];
            unsigned ah[4], al[4];
            #pragma unroll
            for (int i = 0; i < 4; i++) {
                ah[i] = f2tf32(af[i]);
                al[i] = f2tf32(af[i] - __uint_as_float(ah[i]));
            }
            #pragma unroll
            for (int ni = 0; ni < 3; ni++) {
                int nb = nb0 + ni*8;
                float bf0 = Ks[nb + gid][ks + tig    ];
                float bf1 = Ks[nb + gid][ks + tig + 4];
                unsigned bh0 = f2tf32(bf0);
                unsigned bl0 = f2tf32(bf0 - __uint_as_float(bh0));
                unsigned bh1 = f2tf32(bf1);
                unsigned bl1 = f2tf32(bf1 - __uint_as_float(bh1));
                mma_tf32(acc[ni], ah, bh0, bh1);
                mma_tf32(acc[ni], ah, bl0, bl1);
                mma_tf32(acc[ni], al, bh0, bh1);
            }
        }
        __syncthreads();
    }

    atomicAdd(&norms[b*2*Cc + h*Dh + r0], nq0);
    atomicAdd(&norms[b*2*Cc + h*Dh + r1], nq1);
    atomicAdd(&norms[b*2*Cc + Cc + h*Dh + r0], nk0);
    atomicAdd(&norms[b*2*Cc + Cc + h*Dh + r1], nk1);

    float* gp = gram + (long)bh * Dh * Dh;
    #pragma unroll
    for (int ni = 0; ni < 3; ni++) {
        int col = nb0 + ni*8 + tig*2;
        atomicAdd(&gp[(mr + gid    )*Dh + col    ], acc[ni][0]);
        atomicAdd(&gp[(mr + gid    )*Dh + col + 1], acc[ni][1]);
        atomicAdd(&gp[(mr + gid + 8)*Dh + col    ], acc[ni][2]);
        atomicAdd(&gp[(mr + gid + 8)*Dh + col + 1], acc[ni][3]);
    }
}

// ---------------- normalize + temperature + softmax (in place) --------
__global__ void attn_softmax_kernel(const float* __restrict__ temp,
                                    const float* __restrict__ norms,
                                    float* __restrict__ gram)
{
    int idx = blockIdx.x * blockDim.x + threadIdx.x;
    if (idx >= Bq*NHEADS*Dh) return;
    int d  = idx % Dh;
    int bh = idx / Dh;
    int h = bh % NHEADS, b = bh / NHEADS;

    float nq = fmaxf(sqrtf(norms[b*2*Cc + h*Dh + d]), 1e-12f);
    float t = temp[h];
    float* row = gram + (long)bh*Dh*Dh + d*Dh;

    float vals[Dh];
    float mx = -1e30f;
    #pragma unroll
    for (int e = 0; e < Dh; e++) {
        float nk = fmaxf(sqrtf(norms[b*2*Cc + Cc + h*Dh + e]), 1e-12f);
        float v = row[e] / (nq * nk) * t;
        vals[e] = v;
        mx = fmaxf(mx, v);
    }
    float s = 0.f;
    #pragma unroll
    for (int e = 0; e < Dh; e++) { vals[e] = expf(vals[e] - mx); s += vals[e]; }
    float inv = 1.f / s;
    #pragma unroll
    for (int e = 0; e < Dh; e++) row[e] = vals[e] * inv;
}

// ---------------- fold proj into attn ----------------
__global__ void fold_kernel(const float* __restrict__ proj_w,
                            const float* __restrict__ gram,
                            float* __restrict__ Mout)
{
    int idx = blockIdx.x * 256 + threadIdx.x;
    if (idx >= Bq*Cc*Cc) return;
    int he = idx % Cc;
    int o  = (idx / Cc) % Cc;
    int b  = idx / (Cc*Cc);
    int h = he / Dh, e = he % Dh;
    const float* attn = gram + ((long)(b*NHEADS + h)) * Dh * Dh;
    const float* pw = proj_w + (long)o*Cc + h*Dh;
    float s = 0.f;
    #pragma unroll
    for (int dl = 0; dl < Dh; dl++)
        s = fmaf(pw[dl], attn[dl*Dh + e], s);
    Mout[idx] = s;
}

// ---------------- launch ----------------
extern "C" void kernel_launch(void* const* d_in, const int* in_sizes, int n_in,
                              void* d_out, int out_size)
{
    const float* x      = (const float*)d_in[0];
    const float* qkv_w  = (const float*)d_in[1];
    const float* qkv_b  = (const float*)d_in[2];
    const float* dw_w   = (const float*)d_in[3];
    const float* dw_b   = (const float*)d_in[4];
    const float* temp   = (const float*)d_in[5];
    const float* proj_w = (const float*)d_in[6];
    const float* proj_b = (const float*)d_in[7];
    float* out = (float*)d_out;

    float *p_qkv, *p_qkvdw, *p_norms, *p_gram, *p_M;
    cudaGetSymbolAddress((void**)&p_qkv,   g_qkv);
    cudaGetSymbolAddress((void**)&p_qkvdw, g_qkvdw);
    cudaGetSymbolAddress((void**)&p_norms, g_norms);
    cudaGetSymbolAddress((void**)&p_gram,  g_gram);
    cudaGetSymbolAddress((void**)&p_M,     g_M);

    zero_kernel<<<(Bq*NHEADS*Dh*Dh + 255)/256, 256>>>(
        p_norms, Bq*2*Cc, p_gram, Bq*NHEADS*Dh*Dh);

    // GEMM1: qkv = qkv_w @ x (all batches)
    {
        dim3 grid(HWsz/GBN, (C3 + GBM - 1)/GBM, Bq);
        tf32_gemm_bias_kernel<<<grid, 256>>>(
            qkv_w, 0L,
            x, (long)Cc*HWsz,
            p_qkv, (long)C3*HWsz,
            qkv_b, C3, HWsz, Cc);
    }

    // depthwise 3x3 for V channels only
    {
        dim3 grid(Bq*Cc, HWsz/1024);
        dwconv_v_kernel<<<grid, 256>>>(p_qkv, dw_w, dw_b, p_qkvdw);
    }

    // gram + norms with fused dwconv on q,k
    {
        dim3 grid(Bq*NHEADS, GSPLIT);
        gram_dw_kernel<<<grid, 192>>>(p_qkv, dw_w, dw_b, p_gram, p_norms);
    }

    attn_softmax_kernel<<<(Bq*NHEADS*Dh + 255)/256, 256>>>(temp, p_norms, p_gram);

    fold_kernel<<<(Bq*Cc*Cc + 255)/256, 256>>>(proj_w, p_gram, p_M);

    // GEMM4: out = M[b] @ v + proj_b (all batches)
    {
        dim3 grid(HWsz/GBN, (Cc + GBM - 1)/GBM, Bq);
        tf32_gemm_bias_kernel<<<grid, 256>>>(
            p_M, (long)Cc*Cc,
            p_qkvdw + (long)2*Cc*HWsz, (long)C3*HWsz,
            out, (long)Cc*HWsz,
            proj_b, Cc, HWsz, Cc);
    }
}

// round 14
// speedup vs baseline: 1.2593x; 1.2593x over previous
#include <cuda_runtime.h>
#include <math.h>

#define Bq 8
#define Cc 192
#define HH 128
#define WW 128
#define HWsz (HH*WW)      // 16384
#define C3 (3*Cc)         // 576
#define NHEADS 4
#define Dh 48             // C / heads

// ---- scratch (device globals: no cudaMalloc allowed) ----
__device__ float g_qkv[(long)Bq*C3*HWsz];    // after 1x1 conv
__device__ float g_qkvdw[(long)Bq*C3*HWsz];  // after depthwise 3x3
__device__ float g_norms[Bq*2*Cc];           // sum of squares for q,k rows
__device__ float g_gram[Bq*NHEADS*Dh*Dh];    // raw gram -> attn (in place)
__device__ float g_M[Bq*Cc*Cc];              // proj_w folded with attn

// ---------------- zero init ----------------
__global__ void zero_kernel(float* p0, int n0, float* p1, int n1) {
    int i = blockIdx.x * blockDim.x + threadIdx.x;
    if (i < n0) p0[i] = 0.f;
    if (i < n1) p1[i] = 0.f;
}

// ---------------- helpers ----------------
__device__ __forceinline__ unsigned f2tf32(float x) {
    unsigned r;
    asm("cvt.rna.tf32.f32 %0, %1;" : "=r"(r) : "f"(x));
    return r;
}
__device__ __forceinline__ void mma_tf32(float* c, const unsigned* a,
                                         unsigned b0, unsigned b1) {
    asm volatile(
        "mma.sync.aligned.m16n8k8.row.col.f32.tf32.tf32.f32 "
        "{%0,%1,%2,%3}, {%4,%5,%6,%7}, {%8,%9}, {%0,%1,%2,%3};"
        : "+f"(c[0]), "+f"(c[1]), "+f"(c[2]), "+f"(c[3])
        : "r"(a[0]), "r"(a[1]), "r"(a[2]), "r"(a[3]), "r"(b0), "r"(b1));
}

// ---------------- tf32 GEMM (R9 config), staged-cvt + SW-pipelined ----------
#define GBM 128
#define GBN 128
#define GBK 16
__global__ void __launch_bounds__(256)
tf32_gemm_bias_kernel(const float* __restrict__ A, long sA,
                      const float* __restrict__ B, long sB,
                      float* __restrict__ C, long sC,
                      const float* __restrict__ bias,
                      int M, int N, int K)
{
    __shared__ unsigned As[2][GBM][20];    // [m][k], stride 20 (conflict-free)
    __shared__ unsigned Bs[2][GBK][136];   // [k][n], stride 136 (conflict-free)

    const int bz = blockIdx.z;
    const float* Ab = A + (long)bz * sA;
    const float* Bb = B + (long)bz * sB;
    float* Cb = C + (long)bz * sC;

    const int m0 = blockIdx.y * GBM;
    const int n0 = blockIdx.x * GBN;
    const int tid  = threadIdx.x;
    const int wid  = tid >> 5;
    const int lane = tid & 31;
    const int gid  = lane >> 2;
    const int tig  = lane & 3;
    const int wm = (wid & 3) * 32;
    const int wn = (wid >> 2) * 64;

    const int am0 = tid >> 2,          ak0 = (tid & 3) << 2;
    const int am1 = (tid + 256) >> 2,  ak1 = ((tid + 256) & 3) << 2;
    const int bk0 = tid >> 5,          bc0 = (tid & 31) << 2;
    const int bk1 = (tid + 256) >> 5,  bc1 = ((tid + 256) & 31) << 2;

    float acc[2][8][4];
    #pragma unroll
    for (int i = 0; i < 2; i++)
        #pragma unroll
        for (int j = 0; j < 8; j++)
            #pragma unroll
            for (int q = 0; q < 4; q++) acc[i][j][q] = 0.f;

    const int NT = K / GBK;

    float4 ra0, ra1, rb0, rb1;
    auto ldg_tile = [&](int it) {
        const int k0 = it * GBK;
        ra0 = (m0 + am0 < M) ? *(const float4*)(Ab + (long)(m0+am0)*K + k0 + ak0)
                             : make_float4(0.f,0.f,0.f,0.f);
        ra1 = (m0 + am1 < M) ? *(const float4*)(Ab + (long)(m0+am1)*K + k0 + ak1)
                             : make_float4(0.f,0.f,0.f,0.f);
        rb0 = *(const float4*)(Bb + (long)(k0+bk0)*N + n0 + bc0);
        rb1 = *(const float4*)(Bb + (long)(k0+bk1)*N + n0 + bc1);
    };
    auto sts_tile = [&](int s) {
        uint4 w;
        w.x = f2tf32(ra0.x); w.y = f2tf32(ra0.y); w.z = f2tf32(ra0.z); w.w = f2tf32(ra0.w);
        *(uint4*)&As[s][am0][ak0] = w;
        w.x = f2tf32(ra1.x); w.y = f2tf32(ra1.y); w.z = f2tf32(ra1.z); w.w = f2tf32(ra1.w);
        *(uint4*)&As[s][am1][ak1] = w;
        w.x = f2tf32(rb0.x); w.y = f2tf32(rb0.y); w.z = f2tf32(rb0.z); w.w = f2tf32(rb0.w);
        *(uint4*)&Bs[s][bk0][bc0] = w;
        w.x = f2tf32(rb1.x); w.y = f2tf32(rb1.y); w.z = f2tf32(rb1.z); w.w = f2tf32(rb1.w);
        *(uint4*)&Bs[s][bk1][bc1] = w;
    };

    ldg_tile(0);
    sts_tile(0);
    if (NT > 1) ldg_tile(1);
    __syncthreads();

    for (int it = 0; it < NT; it++) {
        if (it + 1 < NT) sts_tile((it + 1) & 1);
        if (it + 2 < NT) ldg_tile(it + 2);
        const int s = it & 1;

        #pragma unroll
        for (int ks = 0; ks < GBK; ks += 8) {
            unsigned a[2][4];
            #pragma unroll
            for (int mi = 0; mi < 2; mi++) {
                int mr = wm + mi*16;
                a[mi][0] = As[s][mr + gid    ][ks + tig    ];
                a[mi][1] = As[s][mr + gid + 8][ks + tig    ];
                a[mi][2] = As[s][mr + gid    ][ks + tig + 4];
                a[mi][3] = As[s][mr + gid + 8][ks + tig + 4];
            }
            #pragma unroll
            for (int ni = 0; ni < 8; ni++) {
                int nb = wn + ni*8;
                unsigned b0 = Bs[s][ks + tig    ][nb + gid];
                unsigned b1 = Bs[s][ks + tig + 4][nb + gid];
                #pragma unroll
                for (int mi = 0; mi < 2; mi++)
                    mma_tf32(acc[mi][ni], a[mi], b0, b1);
            }
        }
        __syncthreads();
    }

    #pragma unroll
    for (int mi = 0; mi < 2; mi++) {
        int r0 = m0 + wm + mi*16 + gid;
        int r1 = r0 + 8;
        float bv0 = (r0 < M && bias) ? bias[r0] : 0.f;
        float bv1 = (r1 < M && bias) ? bias[r1] : 0.f;
        #pragma unroll
        for (int ni = 0; ni < 8; ni++) {
            int col = n0 + wn + ni*8 + tig*2;
            if (r0 < M) {
                float2 v; v.x = acc[mi][ni][0] + bv0; v.y = acc[mi][ni][1] + bv0;
                *(float2*)(Cb + (long)r0*N + col) = v;
            }
            if (r1 < M) {
                float2 v; v.x = acc[mi][ni][2] + bv1; v.y = acc[mi][ni][3] + bv1;
                *(float2*)(Cb + (long)r1*N + col) = v;
            }
        }
    }
}

// ---------------- depthwise 3x3, shuffle halo: 3 LDG.128 per 4 px -----------
// Each warp covers exactly one image row (32 lanes x 4 px = 128 = WW).
// x-halo comes from neighbor lanes via shfl; lane 0 / lane 31 are true image
// boundaries (zero pad).
__global__ void __launch_bounds__(256)
dwconv_kernel(const float* __restrict__ in,
              const float* __restrict__ w,
              const float* __restrict__ bias,
              float* __restrict__ out)
{
    const int bc = blockIdx.x;            // b*C3 + ch
    const int ch = bc % C3;
    const int tid = threadIdx.x;
    const int t = blockIdx.y * 256 + tid;
    const int y    = t >> 5;
    const int lane = tid & 31;
    const int x    = lane << 2;

    const float* ip = in + (long)bc * HWsz;
    float wv[9];
    #pragma unroll
    for (int i = 0; i < 9; i++) wv[i] = w[ch*9 + i];

    float row[3][6];
    #pragma unroll
    for (int r = 0; r < 3; r++) {
        int yy = y + r - 1;
        float4 v = make_float4(0.f, 0.f, 0.f, 0.f);
        if (yy >= 0 && yy < HH)
            v = *(const float4*)(ip + yy*WW + x);
        float lf = __shfl_up_sync(0xFFFFFFFFu, v.w, 1);
        float rt = __shfl_down_sync(0xFFFFFFFFu, v.x, 1);
        if (lane == 0)  lf = 0.f;
        if (lane == 31) rt = 0.f;
        row[r][0] = lf;
        row[r][1] = v.x; row[r][2] = v.y; row[r][3] = v.z; row[r][4] = v.w;
        row[r][5] = rt;
    }

    const float bv = bias[ch];
    float4 ov;
    float* o = (float*)&ov;
    #pragma unroll
    for (int j = 0; j < 4; j++) {
        float acc = bv;
        #pragma unroll
        for (int r = 0; r < 3; r++) {
            acc = fmaf(wv[r*3+0], row[r][j+0], acc);
            acc = fmaf(wv[r*3+1], row[r][j+1], acc);
            acc = fmaf(wv[r*3+2], row[r][j+2], acc);
        }
        o[j] = acc;
    }
    *(float4*)(out + (long)bc * HWsz + y*WW + x) = ov;
}

// ---------------- gram via tf32 mma (fp32 smem, cvt at frag load) ----------
#define GSPLIT 32
#define GCHUNK (HWsz/GSPLIT)   // 512
#define GTP 32                 // pixels per smem tile
#define GST 36                 // pixel stride (floats)
__global__ void __launch_bounds__(192)
gram_mma_kernel(const float* __restrict__ qk,
                float* __restrict__ gram,
                float* __restrict__ norms)
{
    const int bh = blockIdx.x;
    const int split = blockIdx.y;
    const int b = bh >> 2, h = bh & 3;

    const float* qp = qk + ((long)b*C3 + h*Dh) * HWsz;
    const float* kp = qk + ((long)b*C3 + Cc + h*Dh) * HWsz;

    __shared__ float Qs[Dh][GST];
    __shared__ float Ks[Dh][GST];

    const int tid  = threadIdx.x;
    const int wid  = tid >> 5;
    const int lane = tid & 31;
    const int gid  = lane >> 2;
    const int tig  = lane & 3;
    const int mr   = (wid % 3) * 16;
    const int nb0  = (wid / 3) * 24;

    float acc[3][4];
    #pragma unroll
    for (int i = 0; i < 3; i++)
        #pragma unroll
        for (int q = 0; q < 4; q++) acc[i][q] = 0.f;

    const int r0 = tid >> 3;
    const int r1 = r0 + 24;
    const int c0 = (tid & 7) << 2;
    float nq0 = 0.f, nq1 = 0.f, nk0 = 0.f, nk1 = 0.f;

    const int nbase = split * GCHUNK;

    for (int t = 0; t < GCHUNK; t += GTP) {
        long off0 = (long)r0*HWsz + nbase + t + c0;
        long off1 = (long)r1*HWsz + nbase + t + c0;
        float4 v0 = *(const float4*)(qp + off0);
        float4 u0 = *(const float4*)(kp + off0);
        float4 v1 = *(const float4*)(qp + off1);
        float4 u1 = *(const float4*)(kp + off1);
        *(float4*)&Qs[r0][c0] = v0;
        *(float4*)&Ks[r0][c0] = u0;
        *(float4*)&Qs[r1][c0] = v1;
        *(float4*)&Ks[r1][c0] = u1;
        nq0 += v0.x*v0.x + v0.y*v0.y + v0.z*v0.z + v0.w*v0.w;
        nk0 += u0.x*u0.x + u0.y*u0.y + u0.z*u0.z + u0.w*u0.w;
        nq1 += v1.x*v1.x + v1.y*v1.y + v1.z*v1.z + v1.w*v1.w;
        nk1 += u1.x*u1.x + u1.y*u1.y + u1.z*u1.z + u1.w*u1.w;
        __syncthreads();

        #pragma unroll
        for (int ks = 0; ks < GTP; ks += 8) {
            float af[4];
            af[0] = Qs[mr + gid    ][ks + tig    ];
            af[1] = Qs[mr + gid + 8][ks + tig    ];
            af[2] = Qs[mr + gid    ][ks + tig + 4];
            af[3] = Qs[mr + gid + 8][ks + tig + 4];
            unsigned ah[4], al[4];
            #pragma unroll
            for (int i = 0; i < 4; i++) {
                ah[i] = f2tf32(af[i]);
                al[i] = f2tf32(af[i] - __uint_as_float(ah[i]));
            }
            #pragma unroll
            for (int ni = 0; ni < 3; ni++) {
                int nb = nb0 + ni*8;
                float bf0 = Ks[nb + gid][ks + tig    ];
                float bf1 = Ks[nb + gid][ks + tig + 4];
                unsigned bh0 = f2tf32(bf0);
                unsigned bl0 = f2tf32(bf0 - __uint_as_float(bh0));
                unsigned bh1 = f2tf32(bf1);
                unsigned bl1 = f2tf32(bf1 - __uint_as_float(bh1));
                mma_tf32(acc[ni], ah, bh0, bh1);
                mma_tf32(acc[ni], ah, bl0, bl1);
                mma_tf32(acc[ni], al, bh0, bh1);
            }
        }
        __syncthreads();
    }

    atomicAdd(&norms[b*2*Cc + h*Dh + r0], nq0);
    atomicAdd(&norms[b*2*Cc + h*Dh + r1], nq1);
    atomicAdd(&norms[b*2*Cc + Cc + h*Dh + r0], nk0);
    atomicAdd(&norms[b*2*Cc + Cc + h*Dh + r1], nk1);

    float* gp = gram + (long)bh * Dh * Dh;
    #pragma unroll
    for (int ni = 0; ni < 3; ni++) {
        int col = nb0 + ni*8 + tig*2;
        atomicAdd(&gp[(mr + gid    )*Dh + col    ], acc[ni][0]);
        atomicAdd(&gp[(mr + gid    )*Dh + col + 1], acc[ni][1]);
        atomicAdd(&gp[(mr + gid + 8)*Dh + col    ], acc[ni][2]);
        atomicAdd(&gp[(mr + gid + 8)*Dh + col + 1], acc[ni][3]);
    }
}

// ---------------- normalize + temperature + softmax (in place) --------
__global__ void attn_softmax_kernel(const float* __restrict__ temp,
                                    const float* __restrict__ norms,
                                    float* __restrict__ gram)
{
    int idx = blockIdx.x * blockDim.x + threadIdx.x;
    if (idx >= Bq*NHEADS*Dh) return;
    int d  = idx % Dh;
    int bh = idx / Dh;
    int h = bh % NHEADS, b = bh / NHEADS;

    float nq = fmaxf(sqrtf(norms[b*2*Cc + h*Dh + d]), 1e-12f);
    float t = temp[h];
    float* row = gram + (long)bh*Dh*Dh + d*Dh;

    float vals[Dh];
    float mx = -1e30f;
    #pragma unroll
    for (int e = 0; e < Dh; e++) {
        float nk = fmaxf(sqrtf(norms[b*2*Cc + Cc + h*Dh + e]), 1e-12f);
        float v = row[e] / (nq * nk) * t;
        vals[e] = v;
        mx = fmaxf(mx, v);
    }
    float s = 0.f;
    #pragma unroll
    for (int e = 0; e < Dh; e++) { vals[e] = expf(vals[e] - mx); s += vals[e]; }
    float inv = 1.f / s;
    #pragma unroll
    for (int e = 0; e < Dh; e++) row[e] = vals[e] * inv;
}

// ---------------- fold proj into attn ----------------
__global__ void fold_kernel(const float* __restrict__ proj_w,
                            const float* __restrict__ gram,
                            float* __restrict__ Mout)
{
    int idx = blockIdx.x * 256 + threadIdx.x;
    if (idx >= Bq*Cc*Cc) return;
    int he = idx % Cc;
    int o  = (idx / Cc) % Cc;
    int b  = idx / (Cc*Cc);
    int h = he / Dh, e = he % Dh;
    const float* attn = gram + ((long)(b*NHEADS + h)) * Dh * Dh;
    const float* pw = proj_w + (long)o*Cc + h*Dh;
    float s = 0.f;
    #pragma unroll
    for (int dl = 0; dl < Dh; dl++)
        s = fmaf(pw[dl], attn[dl*Dh + e], s);
    Mout[idx] = s;
}

// ---------------- launch ----------------
extern "C" void kernel_launch(void* const* d_in, const int* in_sizes, int n_in,
                              void* d_out, int out_size)
{
    const float* x      = (const float*)d_in[0];
    const float* qkv_w  = (const float*)d_in[1];
    const float* qkv_b  = (const float*)d_in[2];
    const float* dw_w   = (const float*)d_in[3];
    const float* dw_b   = (const float*)d_in[4];
    const float* temp   = (const float*)d_in[5];
    const float* proj_w = (const float*)d_in[6];
    const float* proj_b = (const float*)d_in[7];
    float* out = (float*)d_out;

    float *p_qkv, *p_qkvdw, *p_norms, *p_gram, *p_M;
    cudaGetSymbolAddress((void**)&p_qkv,   g_qkv);
    cudaGetSymbolAddress((void**)&p_qkvdw, g_qkvdw);
    cudaGetSymbolAddress((void**)&p_norms, g_norms);
    cudaGetSymbolAddress((void**)&p_gram,  g_gram);
    cudaGetSymbolAddress((void**)&p_M,     g_M);

    zero_kernel<<<(Bq*NHEADS*Dh*Dh + 255)/256, 256>>>(
        p_norms, Bq*2*Cc, p_gram, Bq*NHEADS*Dh*Dh);

    // GEMM1: qkv = qkv_w @ x (all batches)
    {
        dim3 grid(HWsz/GBN, (C3 + GBM - 1)/GBM, Bq);
        tf32_gemm_bias_kernel<<<grid, 256>>>(
            qkv_w, 0L,
            x, (long)Cc*HWsz,
            p_qkv, (long)C3*HWsz,
            qkv_b, C3, HWsz, Cc);
    }

    // depthwise 3x3 (shuffle halo, all batches)
    {
        dim3 grid(Bq*C3, HWsz/1024);
        dwconv_kernel<<<grid, 256>>>(p_qkv, dw_w, dw_b, p_qkvdw);
    }

    // gram + norms (all batches)
    {
        dim3 grid(Bq*NHEADS, GSPLIT);
        gram_mma_kernel<<<grid, 192>>>(p_qkvdw, p_gram, p_norms);
    }

    attn_softmax_kernel<<<(Bq*NHEADS*Dh + 255)/256, 256>>>(temp, p_norms, p_gram);

    fold_kernel<<<(Bq*Cc*Cc + 255)/256, 256>>>(proj_w, p_gram, p_M);

    // GEMM4: out = M[b] @ v + proj_b (all batches)
    {
        dim3 grid(HWsz/GBN, (Cc + GBM - 1)/GBM, Bq);
        tf32_gemm_bias_kernel<<<grid, 256>>>(
            p_M, (long)Cc*Cc,
            p_qkvdw + (long)2*Cc*HWsz, (long)C3*HWsz,
            out, (long)Cc*HWsz,
            proj_b, Cc, HWsz, Cc);
    }
}

// round 15
// speedup vs baseline: 1.2976x; 1.0304x over previous
#include <cuda_runtime.h>
#include <math.h>

#define Bq 8
#define Cc 192
#define HH 128
#define WW 128
#define HWsz (HH*WW)      // 16384
#define C3 (3*Cc)         // 576
#define NHEADS 4
#define Dh 48             // C / heads

// ---- scratch (device globals: no cudaMalloc allowed) ----
__device__ float g_qkv[(long)Bq*C3*HWsz];    // after 1x1 conv
__device__ float g_qkvdw[(long)Bq*C3*HWsz];  // after depthwise 3x3
__device__ float g_norms[Bq*2*Cc];           // sum of squares for q,k rows
__device__ float g_gram[Bq*NHEADS*Dh*Dh];    // raw gram -> attn (in place)
__device__ float g_M[Bq*Cc*Cc];              // proj_w folded with attn

// ---------------- zero init ----------------
__global__ void zero_kernel(float* p0, int n0, float* p1, int n1) {
    int i = blockIdx.x * blockDim.x + threadIdx.x;
    if (i < n0) p0[i] = 0.f;
    if (i < n1) p1[i] = 0.f;
}

// ---------------- helpers ----------------
__device__ __forceinline__ unsigned f2tf32(float x) {
    unsigned r;
    asm("cvt.rna.tf32.f32 %0, %1;" : "=r"(r) : "f"(x));
    return r;
}
__device__ __forceinline__ void mma_tf32(float* c, const unsigned* a,
                                         unsigned b0, unsigned b1) {
    asm volatile(
        "mma.sync.aligned.m16n8k8.row.col.f32.tf32.tf32.f32 "
        "{%0,%1,%2,%3}, {%4,%5,%6,%7}, {%8,%9}, {%0,%1,%2,%3};"
        : "+f"(c[0]), "+f"(c[1]), "+f"(c[2]), "+f"(c[3])
        : "r"(a[0]), "r"(a[1]), "r"(a[2]), "r"(a[3]), "r"(b0), "r"(b1));
}

// ------- tf32 GEMM: 128x128 block, 128 threads, warp tile 64x64 -------------
// Crossbar-balanced warp tile: (64+64)*16*4 B fragments per 64x64x16 MACs
// = 0.125 B/MAC (matches 128B/cyc smem vs ~1024 MAC/cyc HMMA).
#define GBM 128
#define GBN 128
#define GBK 16
__global__ void __launch_bounds__(128, 2)
tf32_gemm_bias_kernel(const float* __restrict__ A, long sA,
                      const float* __restrict__ B, long sB,
                      float* __restrict__ C, long sC,
                      const float* __restrict__ bias,
                      int M, int N, int K)
{
    __shared__ unsigned As[2][GBM][20];    // [m][k], stride 20 (conflict-free)
    __shared__ unsigned Bs[2][GBK][136];   // [k][n], stride 136 (conflict-free)

    const int bz = blockIdx.z;
    const float* Ab = A + (long)bz * sA;
    const float* Bb = B + (long)bz * sB;
    float* Cb = C + (long)bz * sC;

    const int m0 = blockIdx.y * GBM;
    const int n0 = blockIdx.x * GBN;
    const int tid  = threadIdx.x;
    const int wid  = tid >> 5;
    const int lane = tid & 31;
    const int gid  = lane >> 2;
    const int tig  = lane & 3;
    const int wm = (wid & 1) * 64;     // 2x2 warps, 64x64 tiles
    const int wn = (wid >> 1) * 64;

    // staging: A tile 128x16 = 512 float4 (4/thread), B tile 16x128 = 512 f4
    int am[4], ak[4], bk[4], bc[4];
    #pragma unroll
    for (int i = 0; i < 4; i++) {
        int f = tid + i*128;
        am[i] = f >> 2;  ak[i] = (f & 3) << 2;
        bk[i] = f >> 5;  bc[i] = (f & 31) << 2;
    }

    float acc[4][8][4];
    #pragma unroll
    for (int i = 0; i < 4; i++)
        #pragma unroll
        for (int j = 0; j < 8; j++)
            #pragma unroll
            for (int q = 0; q < 4; q++) acc[i][j][q] = 0.f;

    const int NT = K / GBK;

    float4 ra[4], rb[4];
    auto ldg_tile = [&](int it) {
        const int k0 = it * GBK;
        #pragma unroll
        for (int i = 0; i < 4; i++) {
            ra[i] = (m0 + am[i] < M)
                ? *(const float4*)(Ab + (long)(m0+am[i])*K + k0 + ak[i])
                : make_float4(0.f,0.f,0.f,0.f);
            rb[i] = *(const float4*)(Bb + (long)(k0+bk[i])*N + n0 + bc[i]);
        }
    };
    auto sts_tile = [&](int s) {
        #pragma unroll
        for (int i = 0; i < 4; i++) {
            uint4 w;
            w.x = f2tf32(ra[i].x); w.y = f2tf32(ra[i].y);
            w.z = f2tf32(ra[i].z); w.w = f2tf32(ra[i].w);
            *(uint4*)&As[s][am[i]][ak[i]] = w;
            w.x = f2tf32(rb[i].x); w.y = f2tf32(rb[i].y);
            w.z = f2tf32(rb[i].z); w.w = f2tf32(rb[i].w);
            *(uint4*)&Bs[s][bk[i]][bc[i]] = w;
        }
    };

    ldg_tile(0);
    sts_tile(0);
    if (NT > 1) ldg_tile(1);
    __syncthreads();

    for (int it = 0; it < NT; it++) {
        if (it + 1 < NT) sts_tile((it + 1) & 1);
        if (it + 2 < NT) ldg_tile(it + 2);
        const int s = it & 1;

        #pragma unroll
        for (int ks = 0; ks < GBK; ks += 8) {
            unsigned a[4][4];
            #pragma unroll
            for (int mi = 0; mi < 4; mi++) {
                int mr = wm + mi*16;
                a[mi][0] = As[s][mr + gid    ][ks + tig    ];
                a[mi][1] = As[s][mr + gid + 8][ks + tig    ];
                a[mi][2] = As[s][mr + gid    ][ks + tig + 4];
                a[mi][3] = As[s][mr + gid + 8][ks + tig + 4];
            }
            #pragma unroll
            for (int ni = 0; ni < 8; ni++) {
                int nb = wn + ni*8;
                unsigned b0 = Bs[s][ks + tig    ][nb + gid];
                unsigned b1 = Bs[s][ks + tig + 4][nb + gid];
                #pragma unroll
                for (int mi = 0; mi < 4; mi++)
                    mma_tf32(acc[mi][ni], a[mi], b0, b1);
            }
        }
        __syncthreads();
    }

    #pragma unroll
    for (int mi = 0; mi < 4; mi++) {
        int r0 = m0 + wm + mi*16 + gid;
        int r1 = r0 + 8;
        float bv0 = (r0 < M && bias) ? bias[r0] : 0.f;
        float bv1 = (r1 < M && bias) ? bias[r1] : 0.f;
        #pragma unroll
        for (int ni = 0; ni < 8; ni++) {
            int col = n0 + wn + ni*8 + tig*2;
            if (r0 < M) {
                float2 v; v.x = acc[mi][ni][0] + bv0; v.y = acc[mi][ni][1] + bv0;
                *(float2*)(Cb + (long)r0*N + col) = v;
            }
            if (r1 < M) {
                float2 v; v.x = acc[mi][ni][2] + bv1; v.y = acc[mi][ni][3] + bv1;
                *(float2*)(Cb + (long)r1*N + col) = v;
            }
        }
    }
}

// ---------------- depthwise 3x3, shuffle halo: 3 LDG.128 per 4 px -----------
__global__ void __launch_bounds__(256)
dwconv_kernel(const float* __restrict__ in,
              const float* __restrict__ w,
              const float* __restrict__ bias,
              float* __restrict__ out)
{
    const int bc = blockIdx.x;            // b*C3 + ch
    const int ch = bc % C3;
    const int tid = threadIdx.x;
    const int t = blockIdx.y * 256 + tid;
    const int y    = t >> 5;
    const int lane = tid & 31;
    const int x    = lane << 2;

    const float* ip = in + (long)bc * HWsz;
    float wv[9];
    #pragma unroll
    for (int i = 0; i < 9; i++) wv[i] = w[ch*9 + i];

    float row[3][6];
    #pragma unroll
    for (int r = 0; r < 3; r++) {
        int yy = y + r - 1;
        float4 v = make_float4(0.f, 0.f, 0.f, 0.f);
        if (yy >= 0 && yy < HH)
            v = *(const float4*)(ip + yy*WW + x);
        float lf = __shfl_up_sync(0xFFFFFFFFu, v.w, 1);
        float rt = __shfl_down_sync(0xFFFFFFFFu, v.x, 1);
        if (lane == 0)  lf = 0.f;
        if (lane == 31) rt = 0.f;
        row[r][0] = lf;
        row[r][1] = v.x; row[r][2] = v.y; row[r][3] = v.z; row[r][4] = v.w;
        row[r][5] = rt;
    }

    const float bv = bias[ch];
    float4 ov;
    float* o = (float*)&ov;
    #pragma unroll
    for (int j = 0; j < 4; j++) {
        float acc = bv;
        #pragma unroll
        for (int r = 0; r < 3; r++) {
            acc = fmaf(wv[r*3+0], row[r][j+0], acc);
            acc = fmaf(wv[r*3+1], row[r][j+1], acc);
            acc = fmaf(wv[r*3+2], row[r][j+2], acc);
        }
        o[j] = acc;
    }
    *(float4*)(out + (long)bc * HWsz + y*WW + x) = ov;
}

// ---------------- gram via tf32 mma (fp32 smem, cvt at frag load) ----------
#define GSPLIT 32
#define GCHUNK (HWsz/GSPLIT)   // 512
#define GTP 32                 // pixels per smem tile
#define GST 36                 // pixel stride (floats)
__global__ void __launch_bounds__(192)
gram_mma_kernel(const float* __restrict__ qk,
                float* __restrict__ gram,
                float* __restrict__ norms)
{
    const int bh = blockIdx.x;
    const int split = blockIdx.y;
    const int b = bh >> 2, h = bh & 3;

    const float* qp = qk + ((long)b*C3 + h*Dh) * HWsz;
    const float* kp = qk + ((long)b*C3 + Cc + h*Dh) * HWsz;

    __shared__ float Qs[Dh][GST];
    __shared__ float Ks[Dh][GST];

    const int tid  = threadIdx.x;
    const int wid  = tid >> 5;
    const int lane = tid & 31;
    const int gid  = lane >> 2;
    const int tig  = lane & 3;
    const int mr   = (wid % 3) * 16;
    const int nb0  = (wid / 3) * 24;

    float acc[3][4];
    #pragma unroll
    for (int i = 0; i < 3; i++)
        #pragma unroll
        for (int q = 0; q < 4; q++) acc[i][q] = 0.f;

    const int r0 = tid >> 3;
    const int r1 = r0 + 24;
    const int c0 = (tid & 7) << 2;
    float nq0 = 0.f, nq1 = 0.f, nk0 = 0.f, nk1 = 0.f;

    const int nbase = split * GCHUNK;

    for (int t = 0; t < GCHUNK; t += GTP) {
        long off0 = (long)r0*HWsz + nbase + t + c0;
        long off1 = (long)r1*HWsz + nbase + t + c0;
        float4 v0 = *(const float4*)(qp + off0);
        float4 u0 = *(const float4*)(kp + off0);
        float4 v1 = *(const float4*)(qp + off1);
        float4 u1 = *(const float4*)(kp + off1);
        *(float4*)&Qs[r0][c0] = v0;
        *(float4*)&Ks[r0][c0] = u0;
        *(float4*)&Qs[r1][c0] = v1;
        *(float4*)&Ks[r1][c0] = u1;
        nq0 += v0.x*v0.x + v0.y*v0.y + v0.z*v0.z + v0.w*v0.w;
        nk0 += u0.x*u0.x + u0.y*u0.y + u0.z*u0.z + u0.w*u0.w;
        nq1 += v1.x*v1.x + v1.y*v1.y + v1.z*v1.z + v1.w*v1.w;
        nk1 += u1.x*u1.x + u1.y*u1.y + u1.z*u1.z + u1.w*u1.w;
        __syncthreads();

        #pragma unroll
        for (int ks = 0; ks < GTP; ks += 8) {
            float af[4];
            af[0] = Qs[mr + gid    ][ks + tig    ];
            af[1] = Qs[mr + gid + 8][ks + tig    ];
            af[2] = Qs[mr + gid    ][ks + tig + 4];
            af[3] = Qs[mr + gid + 8][ks + tig + 4];
            unsigned ah[4], al[4];
            #pragma unroll
            for (int i = 0; i < 4; i++) {
                ah[i] = f2tf32(af[i]);
                al[i] = f2tf32(af[i] - __uint_as_float(ah[i]));
            }
            #pragma unroll
            for (int ni = 0; ni < 3; ni++) {
                int nb = nb0 + ni*8;
                float bf0 = Ks[nb + gid][ks + tig    ];
                float bf1 = Ks[nb + gid][ks + tig + 4];
                unsigned bh0 = f2tf32(bf0);
                unsigned bl0 = f2tf32(bf0 - __uint_as_float(bh0));
                unsigned bh1 = f2tf32(bf1);
                unsigned bl1 = f2tf32(bf1 - __uint_as_float(bh1));
                mma_tf32(acc[ni], ah, bh0, bh1);
                mma_tf32(acc[ni], ah, bl0, bl1);
                mma_tf32(acc[ni], al, bh0, bh1);
            }
        }
        __syncthreads();
    }

    atomicAdd(&norms[b*2*Cc + h*Dh + r0], nq0);
    atomicAdd(&norms[b*2*Cc + h*Dh + r1], nq1);
    atomicAdd(&norms[b*2*Cc + Cc + h*Dh + r0], nk0);
    atomicAdd(&norms[b*2*Cc + Cc + h*Dh + r1], nk1);

    float* gp = gram + (long)bh * Dh * Dh;
    #pragma unroll
    for (int ni = 0; ni < 3; ni++) {
        int col = nb0 + ni*8 + tig*2;
        atomicAdd(&gp[(mr + gid    )*Dh + col    ], acc[ni][0]);
        atomicAdd(&gp[(mr + gid    )*Dh + col + 1], acc[ni][1]);
        atomicAdd(&gp[(mr + gid + 8)*Dh + col    ], acc[ni][2]);
        atomicAdd(&gp[(mr + gid + 8)*Dh + col + 1], acc[ni][3]);
    }
}

// ---------------- normalize + temperature + softmax (in place) --------
__global__ void attn_softmax_kernel(const float* __restrict__ temp,
                                    const float* __restrict__ norms,
                                    float* __restrict__ gram)
{
    int idx = blockIdx.x * blockDim.x + threadIdx.x;
    if (idx >= Bq*NHEADS*Dh) return;
    int d  = idx % Dh;
    int bh = idx / Dh;
    int h = bh % NHEADS, b = bh / NHEADS;

    float nq = fmaxf(sqrtf(norms[b*2*Cc + h*Dh + d]), 1e-12f);
    float t = temp[h];
    float* row = gram + (long)bh*Dh*Dh + d*Dh;

    float vals[Dh];
    float mx = -1e30f;
    #pragma unroll
    for (int e = 0; e < Dh; e++) {
        float nk = fmaxf(sqrtf(norms[b*2*Cc + Cc + h*Dh + e]), 1e-12f);
        float v = row[e] / (nq * nk) * t;
        vals[e] = v;
        mx = fmaxf(mx, v);
    }
    float s = 0.f;
    #pragma unroll
    for (int e = 0; e < Dh; e++) { vals[e] = expf(vals[e] - mx); s += vals[e]; }
    float inv = 1.f / s;
    #pragma unroll
    for (int e = 0; e < Dh; e++) row[e] = vals[e] * inv;
}

// ---------------- fold proj into attn ----------------
__global__ void fold_kernel(const float* __restrict__ proj_w,
                            const float* __restrict__ gram,
                            float* __restrict__ Mout)
{
    int idx = blockIdx.x * 256 + threadIdx.x;
    if (idx >= Bq*Cc*Cc) return;
    int he = idx % Cc;
    int o  = (idx / Cc) % Cc;
    int b  = idx / (Cc*Cc);
    int h = he / Dh, e = he % Dh;
    const float* attn = gram + ((long)(b*NHEADS + h)) * Dh * Dh;
    const float* pw = proj_w + (long)o*Cc + h*Dh;
    float s = 0.f;
    #pragma unroll
    for (int dl = 0; dl < Dh; dl++)
        s = fmaf(pw[dl], attn[dl*Dh + e], s);
    Mout[idx] = s;
}

// ---------------- launch ----------------
extern "C" void kernel_launch(void* const* d_in, const int* in_sizes, int n_in,
                              void* d_out, int out_size)
{
    const float* x      = (const float*)d_in[0];
    const float* qkv_w  = (const float*)d_in[1];
    const float* qkv_b  = (const float*)d_in[2];
    const float* dw_w   = (const float*)d_in[3];
    const float* dw_b   = (const float*)d_in[4];
    const float* temp   = (const float*)d_in[5];
    const float* proj_w = (const float*)d_in[6];
    const float* proj_b = (const float*)d_in[7];
    float* out = (float*)d_out;

    float *p_qkv, *p_qkvdw, *p_norms, *p_gram, *p_M;
    cudaGetSymbolAddress((void**)&p_qkv,   g_qkv);
    cudaGetSymbolAddress((void**)&p_qkvdw, g_qkvdw);
    cudaGetSymbolAddress((void**)&p_norms, g_norms);
    cudaGetSymbolAddress((void**)&p_gram,  g_gram);
    cudaGetSymbolAddress((void**)&p_M,     g_M);

    zero_kernel<<<(Bq*NHEADS*Dh*Dh + 255)/256, 256>>>(
        p_norms, Bq*2*Cc, p_gram, Bq*NHEADS*Dh*Dh);

    // GEMM1: qkv = qkv_w @ x (all batches)
    {
        dim3 grid(HWsz/GBN, (C3 + GBM - 1)/GBM, Bq);
        tf32_gemm_bias_kernel<<<grid, 128>>>(
            qkv_w, 0L,
            x, (long)Cc*HWsz,
            p_qkv, (long)C3*HWsz,
            qkv_b, C3, HWsz, Cc);
    }

    // depthwise 3x3 (shuffle halo, all batches)
    {
        dim3 grid(Bq*C3, HWsz/1024);
        dwconv_kernel<<<grid, 256>>>(p_qkv, dw_w, dw_b, p_qkvdw);
    }

    // gram + norms (all batches)
    {
        dim3 grid(Bq*NHEADS, GSPLIT);
        gram_mma_kernel<<<grid, 192>>>(p_qkvdw, p_gram, p_norms);
    }

    attn_softmax_kernel<<<(Bq*NHEADS*Dh + 255)/256, 256>>>(temp, p_norms, p_gram);

    fold_kernel<<<(Bq*Cc*Cc + 255)/256, 256>>>(proj_w, p_gram, p_M);

    // GEMM4: out = M[b] @ v + proj_b (all batches)
    {
        dim3 grid(HWsz/GBN, (Cc + GBM - 1)/GBM, Bq);
        tf32_gemm_bias_kernel<<<grid, 128>>>(
            p_M, (long)Cc*Cc,
            p_qkvdw + (long)2*Cc*HWsz, (long)C3*HWsz,
            out, (long)Cc*HWsz,
            proj_b, Cc, HWsz, Cc);
    }
}

// round 16
// speedup vs baseline: 1.3274x; 1.0230x over previous
#include <cuda_runtime.h>
#include <math.h>

#define Bq 8
#define Cc 192
#define HH 128
#define WW 128
#define HWsz (HH*WW)      // 16384
#define C3 (3*Cc)         // 576
#define NHEADS 4
#define Dh 48             // C / heads

// ---- scratch (device globals: no cudaMalloc allowed) ----
__device__ float g_qkv[(long)Bq*C3*HWsz];    // after 1x1 conv
__device__ float g_qkvdw[(long)Bq*C3*HWsz];  // after depthwise 3x3
__device__ float g_norms[Bq*2*Cc];           // sum of squares for q,k rows
__device__ float g_gram[Bq*NHEADS*Dh*Dh];    // raw gram -> attn (in place)
__device__ float g_M[Bq*Cc*Cc];              // proj_w folded with attn

// ---------------- zero init ----------------
__global__ void zero_kernel(float* p0, int n0, float* p1, int n1) {
    int i = blockIdx.x * blockDim.x + threadIdx.x;
    if (i < n0) p0[i] = 0.f;
    if (i < n1) p1[i] = 0.f;
}

// ---------------- helpers ----------------
__device__ __forceinline__ unsigned f2tf32(float x) {
    unsigned r;
    asm("cvt.rna.tf32.f32 %0, %1;" : "=r"(r) : "f"(x));
    return r;
}
__device__ __forceinline__ void mma_tf32(float* c, const unsigned* a,
                                         unsigned b0, unsigned b1) {
    asm volatile(
        "mma.sync.aligned.m16n8k8.row.col.f32.tf32.tf32.f32 "
        "{%0,%1,%2,%3}, {%4,%5,%6,%7}, {%8,%9}, {%0,%1,%2,%3};"
        : "+f"(c[0]), "+f"(c[1]), "+f"(c[2]), "+f"(c[3])
        : "r"(a[0]), "r"(a[1]), "r"(a[2]), "r"(a[3]), "r"(b0), "r"(b1));
}

// ------- tf32 GEMM: 128x128 block, 128 threads, warp tile 64x64 (R15) -------
#define GBM 128
#define GBN 128
#define GBK 16
__global__ void __launch_bounds__(128, 2)
tf32_gemm_bias_kernel(const float* __restrict__ A, long sA,
                      const float* __restrict__ B, long sB,
                      float* __restrict__ C, long sC,
                      const float* __restrict__ bias,
                      int M, int N, int K)
{
    __shared__ unsigned As[2][GBM][20];    // [m][k], stride 20 (conflict-free)
    __shared__ unsigned Bs[2][GBK][136];   // [k][n], stride 136 (conflict-free)

    const int bz = blockIdx.z;
    const float* Ab = A + (long)bz * sA;
    const float* Bb = B + (long)bz * sB;
    float* Cb = C + (long)bz * sC;

    const int m0 = blockIdx.y * GBM;
    const int n0 = blockIdx.x * GBN;
    const int tid  = threadIdx.x;
    const int wid  = tid >> 5;
    const int lane = tid & 31;
    const int gid  = lane >> 2;
    const int tig  = lane & 3;
    const int wm = (wid & 1) * 64;
    const int wn = (wid >> 1) * 64;

    int am[4], ak[4], bk[4], bc[4];
    #pragma unroll
    for (int i = 0; i < 4; i++) {
        int f = tid + i*128;
        am[i] = f >> 2;  ak[i] = (f & 3) << 2;
        bk[i] = f >> 5;  bc[i] = (f & 31) << 2;
    }

    float acc[4][8][4];
    #pragma unroll
    for (int i = 0; i < 4; i++)
        #pragma unroll
        for (int j = 0; j < 8; j++)
            #pragma unroll
            for (int q = 0; q < 4; q++) acc[i][j][q] = 0.f;

    const int NT = K / GBK;

    float4 ra[4], rb[4];
    auto ldg_tile = [&](int it) {
        const int k0 = it * GBK;
        #pragma unroll
        for (int i = 0; i < 4; i++) {
            ra[i] = (m0 + am[i] < M)
                ? *(const float4*)(Ab + (long)(m0+am[i])*K + k0 + ak[i])
                : make_float4(0.f,0.f,0.f,0.f);
            rb[i] = *(const float4*)(Bb + (long)(k0+bk[i])*N + n0 + bc[i]);
        }
    };
    auto sts_tile = [&](int s) {
        #pragma unroll
        for (int i = 0; i < 4; i++) {
            uint4 w;
            w.x = f2tf32(ra[i].x); w.y = f2tf32(ra[i].y);
            w.z = f2tf32(ra[i].z); w.w = f2tf32(ra[i].w);
            *(uint4*)&As[s][am[i]][ak[i]] = w;
            w.x = f2tf32(rb[i].x); w.y = f2tf32(rb[i].y);
            w.z = f2tf32(rb[i].z); w.w = f2tf32(rb[i].w);
            *(uint4*)&Bs[s][bk[i]][bc[i]] = w;
        }
    };

    ldg_tile(0);
    sts_tile(0);
    if (NT > 1) ldg_tile(1);
    __syncthreads();

    for (int it = 0; it < NT; it++) {
        if (it + 1 < NT) sts_tile((it + 1) & 1);
        if (it + 2 < NT) ldg_tile(it + 2);
        const int s = it & 1;

        #pragma unroll
        for (int ks = 0; ks < GBK; ks += 8) {
            unsigned a[4][4];
            #pragma unroll
            for (int mi = 0; mi < 4; mi++) {
                int mr = wm + mi*16;
                a[mi][0] = As[s][mr + gid    ][ks + tig    ];
                a[mi][1] = As[s][mr + gid + 8][ks + tig    ];
                a[mi][2] = As[s][mr + gid    ][ks + tig + 4];
                a[mi][3] = As[s][mr + gid + 8][ks + tig + 4];
            }
            #pragma unroll
            for (int ni = 0; ni < 8; ni++) {
                int nb = wn + ni*8;
                unsigned b0 = Bs[s][ks + tig    ][nb + gid];
                unsigned b1 = Bs[s][ks + tig + 4][nb + gid];
                #pragma unroll
                for (int mi = 0; mi < 4; mi++)
                    mma_tf32(acc[mi][ni], a[mi], b0, b1);
            }
        }
        __syncthreads();
    }

    #pragma unroll
    for (int mi = 0; mi < 4; mi++) {
        int r0 = m0 + wm + mi*16 + gid;
        int r1 = r0 + 8;
        float bv0 = (r0 < M && bias) ? bias[r0] : 0.f;
        float bv1 = (r1 < M && bias) ? bias[r1] : 0.f;
        #pragma unroll
        for (int ni = 0; ni < 8; ni++) {
            int col = n0 + wn + ni*8 + tig*2;
            if (r0 < M) {
                float2 v; v.x = acc[mi][ni][0] + bv0; v.y = acc[mi][ni][1] + bv0;
                *(float2*)(Cb + (long)r0*N + col) = v;
            }
            if (r1 < M) {
                float2 v; v.x = acc[mi][ni][2] + bv1; v.y = acc[mi][ni][3] + bv1;
                *(float2*)(Cb + (long)r1*N + col) = v;
            }
        }
    }
}

// ------- depthwise 3x3, shuffle halo, 2 output rows per warp ----------------
// Warp computes rows y0, y0+1 of one channel; loads 4 input rows (y0-1..y0+2)
// = 2 LDG.128 per 4 outputs. Halo via shfl (lane 0/31 are image boundaries).
__global__ void __launch_bounds__(256)
dwconv_kernel(const float* __restrict__ in,
              const float* __restrict__ w,
              const float* __restrict__ bias,
              float* __restrict__ out)
{
    const int bc = blockIdx.x;            // b*C3 + ch
    const int ch = bc % C3;
    const int tid = threadIdx.x;
    const int wrp = tid >> 5;             // 0..7
    const int lane = tid & 31;
    const int x    = lane << 2;
    const int y0   = (blockIdx.y << 4) + (wrp << 1);   // 16 rows per block

    const float* ip = in + (long)bc * HWsz;
    float wv[9];
    #pragma unroll
    for (int i = 0; i < 9; i++) wv[i] = w[ch*9 + i];

    // load 4 rows: y0-1, y0, y0+1, y0+2 (with halo via shfl)
    float row[4][6];
    #pragma unroll
    for (int r = 0; r < 4; r++) {
        int yy = y0 + r - 1;
        float4 v = make_float4(0.f, 0.f, 0.f, 0.f);
        if (yy >= 0 && yy < HH)
            v = *(const float4*)(ip + yy*WW + x);
        float lf = __shfl_up_sync(0xFFFFFFFFu, v.w, 1);
        float rt = __shfl_down_sync(0xFFFFFFFFu, v.x, 1);
        if (lane == 0)  lf = 0.f;
        if (lane == 31) rt = 0.f;
        row[r][0] = lf;
        row[r][1] = v.x; row[r][2] = v.y; row[r][3] = v.z; row[r][4] = v.w;
        row[r][5] = rt;
    }

    const float bv = bias[ch];
    #pragma unroll
    for (int dy = 0; dy < 2; dy++) {      // output rows y0+dy
        float4 ov;
        float* o = (float*)&ov;
        #pragma unroll
        for (int j = 0; j < 4; j++) {
            float acc = bv;
            #pragma unroll
            for (int r = 0; r < 3; r++) {
                acc = fmaf(wv[r*3+0], row[dy+r][j+0], acc);
                acc = fmaf(wv[r*3+1], row[dy+r][j+1], acc);
                acc = fmaf(wv[r*3+2], row[dy+r][j+2], acc);
            }
            o[j] = acc;
        }
        *(float4*)(out + (long)bc * HWsz + (y0+dy)*WW + x) = ov;
    }
}

// ---------------- gram via tf32 mma (fp32 smem, cvt at frag load) ----------
#define GSPLIT 32
#define GCHUNK (HWsz/GSPLIT)   // 512
#define GTP 32                 // pixels per smem tile
#define GST 36                 // pixel stride (floats)
__global__ void __launch_bounds__(192)
gram_mma_kernel(const float* __restrict__ qk,
                float* __restrict__ gram,
                float* __restrict__ norms)
{
    const int bh = blockIdx.x;
    const int split = blockIdx.y;
    const int b = bh >> 2, h = bh & 3;

    const float* qp = qk + ((long)b*C3 + h*Dh) * HWsz;
    const float* kp = qk + ((long)b*C3 + Cc + h*Dh) * HWsz;

    __shared__ float Qs[Dh][GST];
    __shared__ float Ks[Dh][GST];

    const int tid  = threadIdx.x;
    const int wid  = tid >> 5;
    const int lane = tid & 31;
    const int gid  = lane >> 2;
    const int tig  = lane & 3;
    const int mr   = (wid % 3) * 16;
    const int nb0  = (wid / 3) * 24;

    float acc[3][4];
    #pragma unroll
    for (int i = 0; i < 3; i++)
        #pragma unroll
        for (int q = 0; q < 4; q++) acc[i][q] = 0.f;

    const int r0 = tid >> 3;
    const int r1 = r0 + 24;
    const int c0 = (tid & 7) << 2;
    float nq0 = 0.f, nq1 = 0.f, nk0 = 0.f, nk1 = 0.f;

    const int nbase = split * GCHUNK;

    for (int t = 0; t < GCHUNK; t += GTP) {
        long off0 = (long)r0*HWsz + nbase + t + c0;
        long off1 = (long)r1*HWsz + nbase + t + c0;
        float4 v0 = *(const float4*)(qp + off0);
        float4 u0 = *(const float4*)(kp + off0);
        float4 v1 = *(const float4*)(qp + off1);
        float4 u1 = *(const float4*)(kp + off1);
        *(float4*)&Qs[r0][c0] = v0;
        *(float4*)&Ks[r0][c0] = u0;
        *(float4*)&Qs[r1][c0] = v1;
        *(float4*)&Ks[r1][c0] = u1;
        nq0 += v0.x*v0.x + v0.y*v0.y + v0.z*v0.z + v0.w*v0.w;
        nk0 += u0.x*u0.x + u0.y*u0.y + u0.z*u0.z + u0.w*u0.w;
        nq1 += v1.x*v1.x + v1.y*v1.y + v1.z*v1.z + v1.w*v1.w;
        nk1 += u1.x*u1.x + u1.y*u1.y + u1.z*u1.z + u1.w*u1.w;
        __syncthreads();

        #pragma unroll
        for (int ks = 0; ks < GTP; ks += 8) {
            float af[4];
            af[0] = Qs[mr + gid    ][ks + tig    ];
            af[1] = Qs[mr + gid + 8][ks + tig    ];
            af[2] = Qs[mr + gid    ][ks + tig + 4];
            af[3] = Qs[mr + gid + 8][ks + tig + 4];
            unsigned ah[4], al[4];
            #pragma unroll
            for (int i = 0; i < 4; i++) {
                ah[i] = f2tf32(af[i]);
                al[i] = f2tf32(af[i] - __uint_as_float(ah[i]));
            }
            #pragma unroll
            for (int ni = 0; ni < 3; ni++) {
                int nb = nb0 + ni*8;
                float bf0 = Ks[nb + gid][ks + tig    ];
                float bf1 = Ks[nb + gid][ks + tig + 4];
                unsigned bh0 = f2tf32(bf0);
                unsigned bl0 = f2tf32(bf0 - __uint_as_float(bh0));
                unsigned bh1 = f2tf32(bf1);
                unsigned bl1 = f2tf32(bf1 - __uint_as_float(bh1));
                mma_tf32(acc[ni], ah, bh0, bh1);
                mma_tf32(acc[ni], ah, bl0, bl1);
                mma_tf32(acc[ni], al, bh0, bh1);
            }
        }
        __syncthreads();
    }

    atomicAdd(&norms[b*2*Cc + h*Dh + r0], nq0);
    atomicAdd(&norms[b*2*Cc + h*Dh + r1], nq1);
    atomicAdd(&norms[b*2*Cc + Cc + h*Dh + r0], nk0);
    atomicAdd(&norms[b*2*Cc + Cc + h*Dh + r1], nk1);

    float* gp = gram + (long)bh * Dh * Dh;
    #pragma unroll
    for (int ni = 0; ni < 3; ni++) {
        int col = nb0 + ni*8 + tig*2;
        atomicAdd(&gp[(mr + gid    )*Dh + col    ], acc[ni][0]);
        atomicAdd(&gp[(mr + gid    )*Dh + col + 1], acc[ni][1]);
        atomicAdd(&gp[(mr + gid + 8)*Dh + col    ], acc[ni][2]);
        atomicAdd(&gp[(mr + gid + 8)*Dh + col + 1], acc[ni][3]);
    }
}

// ---------------- normalize + temperature + softmax (in place) --------
__global__ void attn_softmax_kernel(const float* __restrict__ temp,
                                    const float* __restrict__ norms,
                                    float* __restrict__ gram)
{
    int idx = blockIdx.x * blockDim.x + threadIdx.x;
    if (idx >= Bq*NHEADS*Dh) return;
    int d  = idx % Dh;
    int bh = idx / Dh;
    int h = bh % NHEADS, b = bh / NHEADS;

    float nq = fmaxf(sqrtf(norms[b*2*Cc + h*Dh + d]), 1e-12f);
    float t = temp[h];
    float* row = gram + (long)bh*Dh*Dh + d*Dh;

    float vals[Dh];
    float mx = -1e30f;
    #pragma unroll
    for (int e = 0; e < Dh; e++) {
        float nk = fmaxf(sqrtf(norms[b*2*Cc + Cc + h*Dh + e]), 1e-12f);
        float v = row[e] / (nq * nk) * t;
        vals[e] = v;
        mx = fmaxf(mx, v);
    }
    float s = 0.f;
    #pragma unroll
    for (int e = 0; e < Dh; e++) { vals[e] = expf(vals[e] - mx); s += vals[e]; }
    float inv = 1.f / s;
    #pragma unroll
    for (int e = 0; e < Dh; e++) row[e] = vals[e] * inv;
}

// ---------------- fold proj into attn ----------------
__global__ void fold_kernel(const float* __restrict__ proj_w,
                            const float* __restrict__ gram,
                            float* __restrict__ Mout)
{
    int idx = blockIdx.x * 256 + threadIdx.x;
    if (idx >= Bq*Cc*Cc) return;
    int he = idx % Cc;
    int o  = (idx / Cc) % Cc;
    int b  = idx / (Cc*Cc);
    int h = he / Dh, e = he % Dh;
    const float* attn = gram + ((long)(b*NHEADS + h)) * Dh * Dh;
    const float* pw = proj_w + (long)o*Cc + h*Dh;
    float s = 0.f;
    #pragma unroll
    for (int dl = 0; dl < Dh; dl++)
        s = fmaf(pw[dl], attn[dl*Dh + e], s);
    Mout[idx] = s;
}

// ---------------- launch ----------------
extern "C" void kernel_launch(void* const* d_in, const int* in_sizes, int n_in,
                              void* d_out, int out_size)
{
    const float* x      = (const float*)d_in[0];
    const float* qkv_w  = (const float*)d_in[1];
    const float* qkv_b  = (const float*)d_in[2];
    const float* dw_w   = (const float*)d_in[3];
    const float* dw_b   = (const float*)d_in[4];
    const float* temp   = (const float*)d_in[5];
    const float* proj_w = (const float*)d_in[6];
    const float* proj_b = (const float*)d_in[7];
    float* out = (float*)d_out;

    float *p_qkv, *p_qkvdw, *p_norms, *p_gram, *p_M;
    cudaGetSymbolAddress((void**)&p_qkv,   g_qkv);
    cudaGetSymbolAddress((void**)&p_qkvdw, g_qkvdw);
    cudaGetSymbolAddress((void**)&p_norms, g_norms);
    cudaGetSymbolAddress((void**)&p_gram,  g_gram);
    cudaGetSymbolAddress((void**)&p_M,     g_M);

    zero_kernel<<<(Bq*NHEADS*Dh*Dh + 255)/256, 256>>>(
        p_norms, Bq*2*Cc, p_gram, Bq*NHEADS*Dh*Dh);

    // GEMM1: qkv = qkv_w @ x (all batches)
    {
        dim3 grid(HWsz/GBN, (C3 + GBM - 1)/GBM, Bq);
        tf32_gemm_bias_kernel<<<grid, 128>>>(
            qkv_w, 0L,
            x, (long)Cc*HWsz,
            p_qkv, (long)C3*HWsz,
            qkv_b, C3, HWsz, Cc);
    }

    // depthwise 3x3 (shuffle halo, 2 rows/warp)
    {
        dim3 grid(Bq*C3, HH/16);
        dwconv_kernel<<<grid, 256>>>(p_qkv, dw_w, dw_b, p_qkvdw);
    }

    // gram + norms (all batches)
    {
        dim3 grid(Bq*NHEADS, GSPLIT);
        gram_mma_kernel<<<grid, 192>>>(p_qkvdw, p_gram, p_norms);
    }

    attn_softmax_kernel<<<(Bq*NHEADS*Dh + 255)/256, 256>>>(temp, p_norms, p_gram);

    fold_kernel<<<(Bq*Cc*Cc + 255)/256, 256>>>(proj_w, p_gram, p_M);

    // GEMM4: out = M[b] @ v + proj_b (all batches)
    {
        dim3 grid(HWsz/GBN, (Cc + GBM - 1)/GBM, Bq);
        tf32_gemm_bias_kernel<<<grid, 128>>>(
            p_M, (long)Cc*Cc,
            p_qkvdw + (long)2*Cc*HWsz, (long)C3*HWsz,
            out, (long)Cc*HWsz,
            proj_b, Cc, HWsz, Cc);
    }
}